// round 1
// baseline (speedup 1.0000x reference)
#include <cuda_runtime.h>

#define N_POINTS    32768
#define EMB         64
#define NUM_CLASSES 50
#define NUM_HOUSES  5
#define NUM_WIN     6            // NUM_WINDOWS + 1 (last = frame)
#define BOXES_PER_CLASS (NUM_HOUSES * NUM_WIN)   // 30

// Output layout (float32, concat in reference return order):
//   [0 : N*EMB)                         data
//   [N*EMB : N*EMB + 50*N)              contains (1.0f / 0.0f)
//   [... : ... + 50*30*N)               dists [c][h][w][n]
#define OUT_CONTAINS ((size_t)N_POINTS * EMB)
#define OUT_DISTS    (OUT_CONTAINS + (size_t)NUM_CLASSES * N_POINTS)

__global__ __launch_bounds__(256, 2)
void geom_kernel(const float* __restrict__ data,
                 const float* __restrict__ shape,   // [50][5][6][2][64]
                 float* __restrict__ out)
{
    __shared__ float s_lo[BOXES_PER_CLASS][EMB];
    __shared__ float s_hi[BOXES_PER_CLASS][EMB];

    const int c   = blockIdx.y;
    const int tid = threadIdx.x;
    const int n   = blockIdx.x * 256 + tid;

    // ---- stage this class's 30 boxes (lo = min corners, hi = max corners) ----
    const float* sb = shape + (size_t)c * (BOXES_PER_CLASS * 2 * EMB);
    #pragma unroll
    for (int e = tid; e < BOXES_PER_CLASS * EMB; e += 256) {
        const int box = e >> 6;
        const int d   = e & 63;
        const float a = sb[box * 128 + d];
        const float b = sb[box * 128 + 64 + d];
        s_lo[box][d] = fminf(a, b);
        s_hi[box][d] = fmaxf(a, b);
    }
    __syncthreads();

    // ---- load this thread's point (64 dims) into registers ----
    float4 p[16];
    const float4* dp = reinterpret_cast<const float4*>(data + (size_t)n * EMB);
    #pragma unroll
    for (int i = 0; i < 16; i++) p[i] = dp[i];

    // passthrough: copy data into output once (only one class-slice does it)
    if (blockIdx.y == 0) {
        float4* od = reinterpret_cast<float4*>(out + (size_t)n * EMB);
        #pragma unroll
        for (int i = 0; i < 16; i++) od[i] = p[i];
    }

    float* __restrict__ out_dists = out + OUT_DISTS
                                  + (size_t)c * BOXES_PER_CLASS * N_POINTS + n;

    bool town = false;
    int box = 0;
    #pragma unroll 1
    for (int h = 0; h < NUM_HOUSES; h++) {
        bool anyw = false, frame = false;
        #pragma unroll 1
        for (int w = 0; w < NUM_WIN; w++, box++) {
            const float4* lo4 = reinterpret_cast<const float4*>(s_lo[box]);
            const float4* hi4 = reinterpret_cast<const float4*>(s_hi[box]);
            float sq0 = 0.f, sq1 = 0.f, sq2 = 0.f, sq3 = 0.f;
            #pragma unroll
            for (int i = 0; i < 16; i++) {
                const float4 lo = lo4[i];
                const float4 hi = hi4[i];
                const float4 pp = p[i];
                const float d0 = fmaxf(fmaxf(lo.x - pp.x, pp.x - hi.x), 0.0f);
                const float d1 = fmaxf(fmaxf(lo.y - pp.y, pp.y - hi.y), 0.0f);
                const float d2 = fmaxf(fmaxf(lo.z - pp.z, pp.z - hi.z), 0.0f);
                const float d3 = fmaxf(fmaxf(lo.w - pp.w, pp.w - hi.w), 0.0f);
                sq0 = fmaf(d0, d0, sq0);
                sq1 = fmaf(d1, d1, sq1);
                sq2 = fmaf(d2, d2, sq2);
                sq3 = fmaf(d3, d3, sq3);
            }
            const float sq = (sq0 + sq1) + (sq2 + sq3);

            // inside <=> every per-dim delta == 0 <=> sq == 0 (exact in fp32)
            const bool ins = (sq == 0.0f);
            if (w < NUM_WIN - 1) anyw |= ins;
            else                 frame = ins;

            float dist;
            asm("sqrt.approx.f32 %0, %1;" : "=f"(dist) : "f"(sq));  // sqrt(0)=0
            out_dists[(size_t)box * N_POINTS] = dist;
        }
        town |= (frame && !anyw);
    }

    out[OUT_CONTAINS + (size_t)c * N_POINTS + n] = town ? 1.0f : 0.0f;
}

extern "C" void kernel_launch(void* const* d_in, const int* in_sizes, int n_in,
                              void* d_out, int out_size) {
    const float* data  = (const float*)d_in[0];
    const float* shape = (const float*)d_in[1];
    float* out = (float*)d_out;

    dim3 grid(N_POINTS / 256, NUM_CLASSES);
    geom_kernel<<<grid, 256>>>(data, shape, out);
}

// round 2
// speedup vs baseline: 1.7271x; 1.7271x over previous
#include <cuda_runtime.h>

#define N_POINTS    32768
#define EMB         64
#define NUM_CLASSES 50
#define NUM_HOUSES  5
#define NUM_WIN     6            // NUM_WINDOWS + 1 (last = frame)
#define BOXES       (NUM_HOUSES * NUM_WIN)   // 30

// Output layout (float32, concat in reference return order):
//   [0 : N*EMB)                 data
//   [N*EMB : +50*N)             contains (1.0/0.0)
//   [... : +50*30*N)            dists [c][h][w][n]
#define OUT_CONTAINS ((size_t)N_POINTS * EMB)
#define OUT_DISTS    (OUT_CONTAINS + (size_t)NUM_CLASSES * N_POINTS)

typedef unsigned long long u64;

__device__ __forceinline__ u64 f32x2_sub(u64 a, u64 b) {
    u64 r; asm("sub.rn.f32x2 %0, %1, %2;" : "=l"(r) : "l"(a), "l"(b)); return r;
}
__device__ __forceinline__ u64 f32x2_add(u64 a, u64 b) {
    u64 r; asm("add.rn.f32x2 %0, %1, %2;" : "=l"(r) : "l"(a), "l"(b)); return r;
}
__device__ __forceinline__ u64 f32x2_mul(u64 a, u64 b) {
    u64 r; asm("mul.rn.f32x2 %0, %1, %2;" : "=l"(r) : "l"(a), "l"(b)); return r;
}
__device__ __forceinline__ u64 f32x2_fma(u64 a, u64 b, u64 c) {
    u64 r; asm("fma.rn.f32x2 %0, %1, %2, %3;" : "=l"(r) : "l"(a), "l"(b), "l"(c)); return r;
}
__device__ __forceinline__ u64 pack2(float x, float y) {
    u64 r; asm("mov.b64 %0, {%1, %2};" : "=l"(r) : "f"(x), "f"(y)); return r;
}
__device__ __forceinline__ void unpack2(u64 v, float& x, float& y) {
    asm("mov.b64 {%0, %1}, %2;" : "=f"(x), "=f"(y) : "l"(v));
}

// One 2-dim step: clamp p to [lo,hi] per lane (scalar FMNMX), then packed
// (p - clamped)^2 accumulate. FMA variant accumulates; MUL variant initializes.
#define PAIR_FMA(J, ACC) {                                        \
    const float4 bb = bx[(J)];                                    \
    float px, py; unpack2(p[(J)], px, py);                        \
    const float c0 = fminf(fmaxf(px, bb.x), bb.z);                \
    const float c1 = fminf(fmaxf(py, bb.y), bb.w);                \
    const u64 d = f32x2_sub(p[(J)], pack2(c0, c1));               \
    ACC = f32x2_fma(d, d, ACC); }

#define PAIR_MUL(J, ACC) {                                        \
    const float4 bb = bx[(J)];                                    \
    float px, py; unpack2(p[(J)], px, py);                        \
    const float c0 = fminf(fmaxf(px, bb.x), bb.z);                \
    const float c1 = fminf(fmaxf(py, bb.y), bb.w);                \
    const u64 d = f32x2_sub(p[(J)], pack2(c0, c1));               \
    ACC = f32x2_mul(d, d); }

__global__ __launch_bounds__(256, 2)
void geom_kernel(const float* __restrict__ data,
                 const float* __restrict__ shape,   // [50][5][6][2][64]
                 float* __restrict__ out)
{
    // Interleaved: s_box[box][j] = (lo[2j], lo[2j+1], hi[2j], hi[2j+1])
    __shared__ float4 s_box[BOXES][32];

    const int c   = blockIdx.y;
    const int tid = threadIdx.x;
    const int n   = blockIdx.x * 256 + tid;

    // ---- stage this class's 30 boxes, min/max-normalized, interleaved ----
    const float2* sb2 = reinterpret_cast<const float2*>(
        shape + (size_t)c * (BOXES * 2 * EMB));
    #pragma unroll
    for (int e = tid; e < BOXES * 32; e += 256) {
        const int box = e >> 5;
        const int j   = e & 31;
        const float2 a = sb2[box * 64 + j];        // corner 0, dims 2j,2j+1
        const float2 b = sb2[box * 64 + 32 + j];   // corner 1
        s_box[box][j] = make_float4(fminf(a.x, b.x), fminf(a.y, b.y),
                                    fmaxf(a.x, b.x), fmaxf(a.y, b.y));
    }
    __syncthreads();

    // ---- point: 64 dims kept as 32 packed f32x2 values ----
    u64 p[32];
    const ulonglong2* dp = reinterpret_cast<const ulonglong2*>(
        data + (size_t)n * EMB);
    #pragma unroll
    for (int i = 0; i < 16; i++) {
        const ulonglong2 v = dp[i];
        p[2 * i]     = v.x;
        p[2 * i + 1] = v.y;
    }

    // passthrough copy (one class-slice only)
    if (blockIdx.y == 0) {
        ulonglong2* od = reinterpret_cast<ulonglong2*>(out + (size_t)n * EMB);
        #pragma unroll
        for (int i = 0; i < 16; i++)
            od[i] = make_ulonglong2(p[2 * i], p[2 * i + 1]);
    }

    float* __restrict__ out_dists = out + OUT_DISTS
                                  + (size_t)c * BOXES * N_POINTS + n;

    bool town = false;
    int box = 0;
    #pragma unroll 1
    for (int h = 0; h < NUM_HOUSES; h++) {
        bool anyw = false, frame = false;
        #pragma unroll 2
        for (int w = 0; w < NUM_WIN; w++, box++) {
            const float4* bx = s_box[box];
            u64 a0, a1, a2, a3;
            PAIR_MUL(0, a0) PAIR_MUL(1, a1) PAIR_MUL(2, a2) PAIR_MUL(3, a3)
            #pragma unroll
            for (int j = 4; j < 32; j += 4) {
                PAIR_FMA(j + 0, a0)
                PAIR_FMA(j + 1, a1)
                PAIR_FMA(j + 2, a2)
                PAIR_FMA(j + 3, a3)
            }
            const u64 s = f32x2_add(f32x2_add(a0, a1), f32x2_add(a2, a3));
            float sx, sy; unpack2(s, sx, sy);
            const float sq = sx + sy;

            // inside <=> clamped == p in every dim <=> sq == 0 (exact)
            const bool ins = (sq == 0.0f);
            if (w < NUM_WIN - 1) anyw |= ins;
            else                 frame = ins;

            float dist;
            asm("sqrt.approx.f32 %0, %1;" : "=f"(dist) : "f"(sq));
            out_dists[(size_t)box * N_POINTS] = dist;
        }
        town |= (frame && !anyw);
    }

    out[OUT_CONTAINS + (size_t)c * N_POINTS + n] = town ? 1.0f : 0.0f;
}

extern "C" void kernel_launch(void* const* d_in, const int* in_sizes, int n_in,
                              void* d_out, int out_size) {
    const float* data  = (const float*)d_in[0];
    const float* shape = (const float*)d_in[1];
    float* out = (float*)d_out;

    dim3 grid(N_POINTS / 256, NUM_CLASSES);
    geom_kernel<<<grid, 256>>>(data, shape, out);
}